// round 2
// baseline (speedup 1.0000x reference)
#include <cuda_runtime.h>

#define DIM 16777216

__device__ __forceinline__ float spu(float v) {
    // v >= 0 : v*v - 0.5
    // v <  0 : sigmoid(-v) - 1 = 1/(1+e^v) - 1
    float pos = fmaf(v, v, -0.5f);
    float e = __expf(v);
    float neg = __fdividef(1.0f, 1.0f + e) - 1.0f;
    return (v >= 0.0f) ? pos : neg;
}

__device__ __forceinline__ void spu_elem(float4 xv, float4 lv, float4 uv,
                                         float4& ox, float4& ol, float4& ou) {
    #pragma unroll
    for (int k = 0; k < 4; k++) {
        float xs = (&xv.x)[k];
        float ls = (&lv.x)[k];
        float us = (&uv.x)[k];

        float spu_l = spu(ls);
        float spu_u = spu(us);

        float lo, uo;
        if (ls >= 0.0f) {
            lo = spu_l;
            uo = spu_u;
        } else if (us <= 0.0f) {
            lo = spu_u;
            uo = spu(spu_u);   // faithful: u' = spu(spu(u))
        } else {
            lo = -0.5f;
            uo = spu_u;
        }

        (&ox.x)[k] = spu(xs);
        (&ol.x)[k] = lo;
        (&ou.x)[k] = uo;
    }
}

// 2x float4 per thread; all 6 loads issued up-front (MLP=6), streaming hints.
__global__ void __launch_bounds__(256) spu_box_kernel2(
    const float4* __restrict__ x,
    const float4* __restrict__ l,
    const float4* __restrict__ u,
    float4* __restrict__ out_x,
    float4* __restrict__ out_l,
    float4* __restrict__ out_u)
{
    const int n4 = DIM / 4;
    int base = (blockIdx.x * blockDim.x + threadIdx.x) * 2;
    if (base >= n4) return;
    int i0 = base;
    int i1 = base + 1;

    // Batch all loads first — deep MLP, evict-first (no reuse)
    float4 xv0 = __ldcs(x + i0);
    float4 lv0 = __ldcs(l + i0);
    float4 uv0 = __ldcs(u + i0);
    float4 xv1 = __ldcs(x + i1);
    float4 lv1 = __ldcs(l + i1);
    float4 uv1 = __ldcs(u + i1);

    float4 ox0, ol0, ou0, ox1, ol1, ou1;
    spu_elem(xv0, lv0, uv0, ox0, ol0, ou0);
    spu_elem(xv1, lv1, uv1, ox1, ol1, ou1);

    __stcs(out_x + i0, ox0);
    __stcs(out_x + i1, ox1);
    __stcs(out_l + i0, ol0);
    __stcs(out_l + i1, ol1);
    __stcs(out_u + i0, ou0);
    __stcs(out_u + i1, ou1);
}

extern "C" void kernel_launch(void* const* d_in, const int* in_sizes, int n_in,
                              void* d_out, int out_size) {
    const float4* x = (const float4*)d_in[0];
    const float4* l = (const float4*)d_in[1];
    const float4* u = (const float4*)d_in[2];

    float* out = (float*)d_out;
    float4* out_x = (float4*)(out);
    float4* out_l = (float4*)(out + DIM);
    float4* out_u = (float4*)(out + 2 * DIM);

    const int n4 = DIM / 4;            // 4194304
    const int per_thread = 2;
    int threads = 256;
    int blocks = n4 / (threads * per_thread);   // 8192, exact
    spu_box_kernel2<<<blocks, threads>>>(x, l, u, out_x, out_l, out_u);
}

// round 3
// speedup vs baseline: 1.0327x; 1.0327x over previous
#include <cuda_runtime.h>

#define DIM 16777216

__device__ __forceinline__ float spu(float v) {
    // v >= 0 : v*v - 0.5
    // v <  0 : sigmoid(-v) - 1 = 1/(1+e^v) - 1
    float pos = fmaf(v, v, -0.5f);
    float e = __expf(v);
    float neg = __fdividef(1.0f, 1.0f + e) - 1.0f;
    return (v >= 0.0f) ? pos : neg;
}

__global__ void __launch_bounds__(256) spu_box_kernel(
    const float4* __restrict__ x,
    const float4* __restrict__ l,
    const float4* __restrict__ u,
    float4* __restrict__ out_x,
    float4* __restrict__ out_l,
    float4* __restrict__ out_u)
{
    const int n4 = DIM / 4;
    int i = blockIdx.x * blockDim.x + threadIdx.x;
    if (i >= n4) return;

    // Contiguous per-warp access, streaming (evict-first) hints
    float4 xv = __ldcs(x + i);
    float4 lv = __ldcs(l + i);
    float4 uv = __ldcs(u + i);

    float4 ox, ol, ou;

    #pragma unroll
    for (int k = 0; k < 4; k++) {
        float xs = (&xv.x)[k];
        float ls = (&lv.x)[k];
        float us = (&uv.x)[k];

        float spu_l = spu(ls);
        float spu_u = spu(us);

        float lo, uo;
        if (ls >= 0.0f) {
            lo = spu_l;
            uo = spu_u;
        } else if (us <= 0.0f) {
            lo = spu_u;
            uo = spu(spu_u);   // faithful: u' = spu(spu(u))
        } else {
            lo = -0.5f;
            uo = spu_u;
        }

        (&ox.x)[k] = spu(xs);
        (&ol.x)[k] = lo;
        (&ou.x)[k] = uo;
    }

    __stcs(out_x + i, ox);
    __stcs(out_l + i, ol);
    __stcs(out_u + i, ou);
}

extern "C" void kernel_launch(void* const* d_in, const int* in_sizes, int n_in,
                              void* d_out, int out_size) {
    const float4* x = (const float4*)d_in[0];
    const float4* l = (const float4*)d_in[1];
    const float4* u = (const float4*)d_in[2];

    float* out = (float*)d_out;
    float4* out_x = (float4*)(out);
    float4* out_l = (float4*)(out + DIM);
    float4* out_u = (float4*)(out + 2 * DIM);

    const int n4 = DIM / 4;            // 4194304
    int threads = 256;
    int blocks = n4 / threads;         // 16384, exact
    spu_box_kernel<<<blocks, threads>>>(x, l, u, out_x, out_l, out_u);
}